// round 16
// baseline (speedup 1.0000x reference)
#include <cuda_runtime.h>
#include <cuda_bf16.h>

#define NT 128              // threads per CTA
#define QC 64               // q's per CTA chunk
#define NPAIR (QC / 2)      // 32 q-pairs in shared
#define PPT 8               // points per thread (128*8 = 1024 = P)
#define MARGIN 0.01f
#define FIXED_SCALE 4294967296.0
#define MAXBP (128 * 1024)
#define MAXS 16
#define MAXB 1024

// Exclusive-slot partial mins: g_part[(b*P+p)*S + chunk]. Every slot is
// rewritten by its owning CTA on every replay -> no reset needed.
__device__ float        g_part[MAXBP * MAXS];     // 8 MB static scratch
__device__ unsigned int g_bdone[MAXB];            // per-batch completed chunks
__device__ long long    g_acc;                    // fixed-point loss sum
__device__ unsigned int g_count;                  // CTA completion counter

struct Rot { float r[9]; };

__device__ __forceinline__ Rot quat_rot(const float* __restrict__ q) {
    float s = q[0], u = q[1], v = q[2], w = q[3];
    Rot R;
    R.r[0] = 1.f - 2.f * (v * v + w * w);
    R.r[1] = 2.f * (u * v - s * w);
    R.r[2] = 2.f * (u * w + s * v);
    R.r[3] = 2.f * (u * v + s * w);
    R.r[4] = 1.f - 2.f * (u * u + w * w);
    R.r[5] = 2.f * (v * w - s * u);
    R.r[6] = 2.f * (u * w - s * v);
    R.r[7] = 2.f * (v * w + s * u);
    R.r[8] = 1.f - 2.f * (u * u + v * v);
    return R;
}

// ---- packed f32x2 helpers (Blackwell FFMA2) ----
__device__ __forceinline__ double ffma2(double a, double b, double c) {
    double d;
    asm("fma.rn.f32x2 %0, %1, %2, %3;" : "=d"(d) : "d"(a), "d"(b), "d"(c));
    return d;
}
__device__ __forceinline__ double splat2(float x) {
    double d;
    asm("mov.b64 %0, {%1, %1};" : "=d"(d) : "f"(x));
    return d;
}
__device__ __forceinline__ float lo32(double d) { return __int_as_float(__double2loint(d)); }
__device__ __forceinline__ float hi32(double d) { return __int_as_float(__double2hiint(d)); }

__global__ void __launch_bounds__(NT)
add_loss_kernel(const float* __restrict__ poses_pred,
                const float* __restrict__ poses_target,
                const int*   __restrict__ labels,
                const float* __restrict__ points,
                const int*   __restrict__ symmetry,
                float* __restrict__ out,
                int B, int C, int P, int S)
{
    __shared__ float4 sA[NPAIR];   // (x2x_2j, x2x_2j+1, x2y_2j, x2y_2j+1)
    __shared__ float4 sB[NPAIR];   // (x2z_2j, x2z_2j+1, |x2_2j|^2, |x2_2j+1|^2)
    __shared__ double swarp[NT / 32];
    __shared__ int    s_last;

    const int b    = blockIdx.x;
    const int yc   = blockIdx.y;
    const int tid  = threadIdx.x;
    const int lane = tid & 31;
    const int wid  = tid >> 5;
    const unsigned int total_ctas = gridDim.x * gridDim.y;

    long long ll_acc = 0;                 // tid 0 only

    const int label = labels[b];
    if (label > 0) {
        const bool sym = symmetry[label] > 0;
        const float* mp = points + (size_t)label * P * 3;
        Rot R1 = quat_rot(poses_pred   + ((size_t)b * C + label) * 4);
        Rot R2 = quat_rot(poses_target + ((size_t)b * C + label) * 4);

        if (!sym) {
            if (yc == 0) {
                // ADD: d = |(R1-R2) p|^2 — exact by linearity, one CTA per batch
                float D[9];
                #pragma unroll
                for (int i = 0; i < 9; i++) D[i] = R1.r[i] - R2.r[i];
                double v = 0.0;
                #pragma unroll
                for (int k = 0; k < PPT; k++) {
                    int p = k * NT + tid;
                    if (p < P) {
                        float a = mp[3*p], bb = mp[3*p+1], c = mp[3*p+2];
                        float dx = D[0]*a + D[1]*bb + D[2]*c;
                        float dy = D[3]*a + D[4]*bb + D[5]*c;
                        float dz = D[6]*a + D[7]*bb + D[8]*c;
                        float d = dx*dx + dy*dy + dz*dz;
                        v += (double)fmaxf(0.5f * d - MARGIN, 0.f);
                    }
                }
                #pragma unroll
                for (int off = 16; off > 0; off >>= 1)
                    v += __shfl_down_sync(0xFFFFFFFFu, v, off);
                if (lane == 0) swarp[wid] = v;
                __syncthreads();
                if (tid == 0) {
                    double bsum = 0.0;
                    #pragma unroll
                    for (int w = 0; w < NT / 32; w++) bsum += swarp[w];
                    ll_acc += (long long)llrint(bsum * FIXED_SCALE);
                }
            }
        } else {
            // ---- ADD-S: explicit rotations (R1,R2 need NOT be orthogonal --
            // reference quaternions are unnormalized!) ----
            const int q0 = yc * QC;
            const int npr = min(NPAIR, (P - q0) >> 1);
            if (tid < npr) {
                int j = tid;
                int qa = q0 + 2 * j, qb = qa + 1;
                float a0 = mp[3*qa], b0 = mp[3*qa+1], c0 = mp[3*qa+2];
                float a1 = mp[3*qb], b1 = mp[3*qb+1], c1 = mp[3*qb+2];
                float x0 = R2.r[0]*a0 + R2.r[1]*b0 + R2.r[2]*c0;
                float y0 = R2.r[3]*a0 + R2.r[4]*b0 + R2.r[5]*c0;
                float z0 = R2.r[6]*a0 + R2.r[7]*b0 + R2.r[8]*c0;
                float x1 = R2.r[0]*a1 + R2.r[1]*b1 + R2.r[2]*c1;
                float y1 = R2.r[3]*a1 + R2.r[4]*b1 + R2.r[5]*c1;
                float z1 = R2.r[6]*a1 + R2.r[7]*b1 + R2.r[8]*c1;
                sA[j] = make_float4(x0, x1, y0, y1);
                sB[j] = make_float4(z0, z1,
                                    x0*x0 + y0*y0 + z0*z0,
                                    x1*x1 + y1*y1 + z1*z1);
            }
            __syncthreads();

            // prologue: rotate p by R1 (explicit), splat -2*x1
            float  n1v[PPT];
            double Ax[PPT], Ay[PPT], Az[PPT];
            #pragma unroll
            for (int k = 0; k < PPT; k++) {
                int p = k * NT + tid;
                float a = 0.f, bb = 0.f, c = 0.f;
                if (p < P) { a = mp[3*p]; bb = mp[3*p+1]; c = mp[3*p+2]; }
                float x = R1.r[0]*a + R1.r[1]*bb + R1.r[2]*c;
                float y = R1.r[3]*a + R1.r[4]*bb + R1.r[5]*c;
                float z = R1.r[6]*a + R1.r[7]*bb + R1.r[8]*c;
                Ax[k] = splat2(-2.f*x); Ay[k] = splat2(-2.f*y); Az[k] = splat2(-2.f*z);
                n1v[k] = x*x + y*y + z*z;
            }

            const float INF = 3.4028235e38f;
            float m0[PPT], m1[PPT];
            #pragma unroll
            for (int k = 0; k < PPT; k++) { m0[k] = INF; m1[k] = INF; }

            const double2* __restrict__ pA = (const double2*)sA;
            const double2* __restrict__ pB = (const double2*)sB;
            #pragma unroll 8
            for (int j = 0; j < npr; j++) {
                double2 v1 = pA[j];
                double2 v2 = pB[j];
                #pragma unroll
                for (int k = 0; k < PPT; k++) {
                    double t = ffma2(Ax[k], v1.x, ffma2(Ay[k], v1.y, ffma2(Az[k], v2.x, v2.y)));
                    m0[k] = fminf(m0[k], lo32(t));
                    m1[k] = fminf(m1[k], hi32(t));
                }
            }

            // exclusive-slot coalesced STG epilogue (no atomics)
            #pragma unroll
            for (int k = 0; k < PPT; k++) {
                int p = k * NT + tid;
                if (p < P)
                    g_part[((size_t)b * P + p) * S + yc] = n1v[k] + fminf(m0[k], m1[k]);
            }
            __threadfence();
            __syncthreads();   // all threads' stores fenced before the counter bump

            // last of S chunk-CTAs for this batch finalizes inline
            if (tid == 0)
                s_last = (atomicAdd(&g_bdone[b], 1u) == (unsigned)(S - 1)) ? 1 : 0;
            __syncthreads();

            if (s_last) {
                double v = 0.0;
                #pragma unroll
                for (int k = 0; k < PPT; k++) {
                    int p = k * NT + tid;
                    if (p < P) {
                        const float4* row = (const float4*)&g_part[((size_t)b * P + p) * S];
                        float mn = INF;
                        #pragma unroll
                        for (int c4 = 0; c4 < MAXS / 4; c4++) {
                            if (c4 * 4 < S) {
                                float4 f = row[c4];
                                mn = fminf(mn, fminf(fminf(f.x, f.y), fminf(f.z, f.w)));
                            }
                        }
                        v += (double)fmaxf(0.5f * mn - MARGIN, 0.f);
                    }
                }
                #pragma unroll
                for (int off = 16; off > 0; off >>= 1)
                    v += __shfl_down_sync(0xFFFFFFFFu, v, off);
                if (lane == 0) swarp[wid] = v;
                __syncthreads();
                if (tid == 0) {
                    double bsum = 0.0;
                    #pragma unroll
                    for (int w = 0; w < NT / 32; w++) bsum += swarp[w];
                    ll_acc += (long long)llrint(bsum * FIXED_SCALE);
                    g_bdone[b] = 0u;                     // reset for next replay
                }
            }
        }
    }

    // ---- CTA exit: contribute, then last CTA publishes & resets ----
    if (tid == 0) {
        if (ll_acc != 0)
            atomicAdd((unsigned long long*)&g_acc, (unsigned long long)ll_acc);
        __threadfence();
        unsigned int prev = atomicAdd(&g_count, 1u);
        if (prev == total_ctas - 1) {
            long long acc = (long long)atomicAdd((unsigned long long*)&g_acc, 0ull);
            out[0] = (float)(((double)acc / FIXED_SCALE) / ((double)B * (double)P));
            g_acc  = 0;
            g_count = 0;
            __threadfence();
        }
    }
}

extern "C" void kernel_launch(void* const* d_in, const int* in_sizes, int n_in,
                              void* d_out, int out_size)
{
    const float* poses_pred   = (const float*)d_in[0];
    const float* poses_target = (const float*)d_in[1];
    const int*   poses_labels = (const int*)d_in[2];
    const float* points       = (const float*)d_in[3];
    const int*   symmetry     = (const int*)d_in[4];
    float* out = (float*)d_out;

    const int B = in_sizes[2];                 // labels: [B]
    const int C = in_sizes[4];                 // symmetry: [C]
    const int P = in_sizes[3] / (C * 3);       // points: [C,P,3]
    const int S = (P + QC - 1) / QC;           // q-chunks per batch (16 for P=1024)

    dim3 grid(B, S);
    add_loss_kernel<<<grid, NT>>>(poses_pred, poses_target, poses_labels,
                                  points, symmetry, out, B, C, P, S);
}

// round 17
// speedup vs baseline: 1.1251x; 1.1251x over previous
#include <cuda_runtime.h>
#include <cuda_bf16.h>

#define NT 64               // 2 warps per CTA -> finer steal grain, more resident CTAs
#define QC 64               // q's per chunk
#define NPAIR (QC / 2)      // 32 q-pairs in shared
#define PPT 8               // points per thread (64*8 = 512 = one p-half)
#define PHALF 512
#define SUBS 32             // chunks per batch: 2 p-halves x 16 q-chunks
#define MARGIN 0.01f
#define FIXED_SCALE 4294967296.0
#define MAXBP (128 * 1024)
#define MAXB 1024

// Exact, order-independent state. Zero-init at load; every piece reset by its
// consumer so graph replays start clean.
__device__ unsigned int g_keys[MAXBP];   // per-(b,p) min key; 0 == +inf
__device__ unsigned int g_bdone[MAXB];   // per-batch completed sym chunks
__device__ long long    g_acc;           // fixed-point deterministic loss sum
__device__ unsigned int g_count;         // CTA completion counter

struct Rot { float r[9]; };

__device__ __forceinline__ Rot quat_rot(const float* __restrict__ q) {
    float s = q[0], u = q[1], v = q[2], w = q[3];
    Rot R;
    R.r[0] = 1.f - 2.f * (v * v + w * w);
    R.r[1] = 2.f * (u * v - s * w);
    R.r[2] = 2.f * (u * w + s * v);
    R.r[3] = 2.f * (u * v + s * w);
    R.r[4] = 1.f - 2.f * (u * u + w * w);
    R.r[5] = 2.f * (v * w - s * u);
    R.r[6] = 2.f * (u * w - s * v);
    R.r[7] = 2.f * (v * w + s * u);
    R.r[8] = 1.f - 2.f * (u * u + v * v);
    return R;
}

// ---- packed f32x2 helpers (Blackwell FFMA2) ----
__device__ __forceinline__ double ffma2(double a, double b, double c) {
    double d;
    asm("fma.rn.f32x2 %0, %1, %2, %3;" : "=d"(d) : "d"(a), "d"(b), "d"(c));
    return d;
}
__device__ __forceinline__ double splat2(float x) {
    double d;
    asm("mov.b64 %0, {%1, %1};" : "=d"(d) : "f"(x));
    return d;
}
__device__ __forceinline__ float lo32(double d) { return __int_as_float(__double2loint(d)); }
__device__ __forceinline__ float hi32(double d) { return __int_as_float(__double2hiint(d)); }

// monotone-DEcreasing float->uint key: max(key) == min(float); key 0 == +inf
__device__ __forceinline__ unsigned int kk_of(float f) {
    unsigned int u = __float_as_uint(f);
    unsigned int k = (u & 0x80000000u) ? ~u : (u | 0x80000000u);
    return ~k;
}
__device__ __forceinline__ float f_of_kk(unsigned int kk) {
    unsigned int k = ~kk;
    unsigned int u = (k & 0x80000000u) ? (k ^ 0x80000000u) : ~k;
    return __uint_as_float(u);
}

__global__ void __launch_bounds__(NT)
add_loss_kernel(const float* __restrict__ poses_pred,
                const float* __restrict__ poses_target,
                const int*   __restrict__ labels,
                const float* __restrict__ points,
                const int*   __restrict__ symmetry,
                float* __restrict__ out,
                int B, int C, int P)
{
    __shared__ float4 sA[NPAIR];   // (x2x_2j, x2x_2j+1, x2y_2j, x2y_2j+1)
    __shared__ float4 sB[NPAIR];   // (x2z_2j, x2z_2j+1, |x2_2j|^2, |x2_2j+1|^2)
    __shared__ double swarp[NT / 32];
    __shared__ int    s_last;

    const int b    = blockIdx.x;
    const int sub  = blockIdx.y;          // 0..SUBS-1
    const int pc   = sub >> 4;            // p-half (0/1)
    const int yq   = sub & 15;            // q-chunk
    const int tid  = threadIdx.x;
    const int lane = tid & 31;
    const int wid  = tid >> 5;
    const unsigned int total_ctas = gridDim.x * gridDim.y;

    long long ll_acc = 0;                 // tid 0 only

    const int label = labels[b];
    if (label > 0) {
        const bool sym = symmetry[label] > 0;
        const float* mp = points + (size_t)label * P * 3;
        Rot R1 = quat_rot(poses_pred   + ((size_t)b * C + label) * 4);
        Rot R2 = quat_rot(poses_target + ((size_t)b * C + label) * 4);

        if (!sym) {
            if (yq == 0) {
                // ADD: d = |(R1-R2) p|^2 — exact by linearity; this CTA's p-half
                float D[9];
                #pragma unroll
                for (int i = 0; i < 9; i++) D[i] = R1.r[i] - R2.r[i];
                double v = 0.0;
                #pragma unroll
                for (int k = 0; k < PPT; k++) {
                    int p = pc * PHALF + k * NT + tid;
                    if (p < P) {
                        float a = mp[3*p], bb = mp[3*p+1], c = mp[3*p+2];
                        float dx = D[0]*a + D[1]*bb + D[2]*c;
                        float dy = D[3]*a + D[4]*bb + D[5]*c;
                        float dz = D[6]*a + D[7]*bb + D[8]*c;
                        float d = dx*dx + dy*dy + dz*dz;
                        v += (double)fmaxf(0.5f * d - MARGIN, 0.f);
                    }
                }
                #pragma unroll
                for (int off = 16; off > 0; off >>= 1)
                    v += __shfl_down_sync(0xFFFFFFFFu, v, off);
                if (lane == 0) swarp[wid] = v;
                __syncthreads();
                if (tid == 0) {
                    double bsum = 0.0;
                    #pragma unroll
                    for (int w = 0; w < NT / 32; w++) bsum += swarp[w];
                    ll_acc += (long long)llrint(bsum * FIXED_SCALE);
                }
            }
        } else {
            // ---- ADD-S: explicit rotations (quats unnormalized!) ----
            const int q0 = yq * QC;
            const int npr = min(NPAIR, (P - q0) >> 1);
            if (tid < npr) {
                int j = tid;
                int qa = q0 + 2 * j, qb = qa + 1;
                float a0 = mp[3*qa], b0 = mp[3*qa+1], c0 = mp[3*qa+2];
                float a1 = mp[3*qb], b1 = mp[3*qb+1], c1 = mp[3*qb+2];
                float x0 = R2.r[0]*a0 + R2.r[1]*b0 + R2.r[2]*c0;
                float y0 = R2.r[3]*a0 + R2.r[4]*b0 + R2.r[5]*c0;
                float z0 = R2.r[6]*a0 + R2.r[7]*b0 + R2.r[8]*c0;
                float x1 = R2.r[0]*a1 + R2.r[1]*b1 + R2.r[2]*c1;
                float y1 = R2.r[3]*a1 + R2.r[4]*b1 + R2.r[5]*c1;
                float z1 = R2.r[6]*a1 + R2.r[7]*b1 + R2.r[8]*c1;
                sA[j] = make_float4(x0, x1, y0, y1);
                sB[j] = make_float4(z0, z1,
                                    x0*x0 + y0*y0 + z0*z0,
                                    x1*x1 + y1*y1 + z1*z1);
            }
            __syncthreads();

            // prologue: rotate own p-half by R1, splat -2*x1
            float  n1v[PPT];
            double Ax[PPT], Ay[PPT], Az[PPT];
            #pragma unroll
            for (int k = 0; k < PPT; k++) {
                int p = pc * PHALF + k * NT + tid;
                float a = 0.f, bb = 0.f, c = 0.f;
                if (p < P) { a = mp[3*p]; bb = mp[3*p+1]; c = mp[3*p+2]; }
                float x = R1.r[0]*a + R1.r[1]*bb + R1.r[2]*c;
                float y = R1.r[3]*a + R1.r[4]*bb + R1.r[5]*c;
                float z = R1.r[6]*a + R1.r[7]*bb + R1.r[8]*c;
                Ax[k] = splat2(-2.f*x); Ay[k] = splat2(-2.f*y); Az[k] = splat2(-2.f*z);
                n1v[k] = x*x + y*y + z*z;
            }

            const float INF = 3.4028235e38f;
            float m0[PPT], m1[PPT];
            #pragma unroll
            for (int k = 0; k < PPT; k++) { m0[k] = INF; m1[k] = INF; }

            const double2* __restrict__ pA = (const double2*)sA;
            const double2* __restrict__ pB = (const double2*)sB;
            #pragma unroll 8
            for (int j = 0; j < npr; j++) {
                double2 v1 = pA[j];
                double2 v2 = pB[j];
                #pragma unroll
                for (int k = 0; k < PPT; k++) {
                    double t = ffma2(Ax[k], v1.x, ffma2(Ay[k], v1.y, ffma2(Az[k], v2.x, v2.y)));
                    m0[k] = fminf(m0[k], lo32(t));
                    m1[k] = fminf(m1[k], hi32(t));
                }
            }

            // coalesced atomicMax epilogue (R13-proven: REDG distinct addrs is cheap)
            #pragma unroll
            for (int k = 0; k < PPT; k++) {
                int p = pc * PHALF + k * NT + tid;
                if (p < P) {
                    float d = n1v[k] + fminf(m0[k], m1[k]);
                    atomicMax(&g_keys[(size_t)b * P + p], kk_of(d));
                }
            }
            __threadfence();
            __syncthreads();   // all threads' maxes fenced before counter bump

            // last of SUBS chunk-CTAs for this batch finalizes inline
            if (tid == 0)
                s_last = (atomicAdd(&g_bdone[b], 1u) == (unsigned)(SUBS - 1)) ? 1 : 0;
            __syncthreads();

            if (s_last) {
                double v = 0.0;
                for (int p = tid; p < P; p += NT) {
                    size_t idx = (size_t)b * P + p;
                    unsigned int kk = g_keys[idx];
                    g_keys[idx] = 0u;                    // reset for next replay
                    v += (double)fmaxf(0.5f * f_of_kk(kk) - MARGIN, 0.f);
                }
                #pragma unroll
                for (int off = 16; off > 0; off >>= 1)
                    v += __shfl_down_sync(0xFFFFFFFFu, v, off);
                if (lane == 0) swarp[wid] = v;
                __syncthreads();
                if (tid == 0) {
                    double bsum = 0.0;
                    #pragma unroll
                    for (int w = 0; w < NT / 32; w++) bsum += swarp[w];
                    ll_acc += (long long)llrint(bsum * FIXED_SCALE);
                    g_bdone[b] = 0u;                     // reset for next replay
                }
            }
        }
    }

    // ---- CTA exit: contribute, then last CTA publishes & resets ----
    if (tid == 0) {
        if (ll_acc != 0)
            atomicAdd((unsigned long long*)&g_acc, (unsigned long long)ll_acc);
        __threadfence();
        unsigned int prev = atomicAdd(&g_count, 1u);
        if (prev == total_ctas - 1) {
            long long acc = (long long)atomicAdd((unsigned long long*)&g_acc, 0ull);
            out[0] = (float)(((double)acc / FIXED_SCALE) / ((double)B * (double)P));
            g_acc  = 0;
            g_count = 0;
            __threadfence();
        }
    }
}

extern "C" void kernel_launch(void* const* d_in, const int* in_sizes, int n_in,
                              void* d_out, int out_size)
{
    const float* poses_pred   = (const float*)d_in[0];
    const float* poses_target = (const float*)d_in[1];
    const int*   poses_labels = (const int*)d_in[2];
    const float* points       = (const float*)d_in[3];
    const int*   symmetry     = (const int*)d_in[4];
    float* out = (float*)d_out;

    const int B = in_sizes[2];                 // labels: [B]
    const int C = in_sizes[4];                 // symmetry: [C]
    const int P = in_sizes[3] / (C * 3);       // points: [C,P,3]

    dim3 grid(B, SUBS);
    add_loss_kernel<<<grid, NT>>>(poses_pred, poses_target, poses_labels,
                                  points, symmetry, out, B, C, P);
}